// round 4
// baseline (speedup 1.0000x reference)
#include <cuda_runtime.h>

#define TS    100
#define BB    256
#define DOBS  64
#define DFEAT 512
#define DLAT  512
#define DOUTD 64

// d_out layout (element offsets): outs, hs, thetas, ys, delta_outs
#define OUTS_OFF 0
#define HS_OFF   (TS*BB*DOUTD)
#define TH_OFF   (HS_OFF + TS*BB*DLAT)
#define YS_OFF   (TH_OFF + TS*BB*DLAT)
#define DO_OFF   (YS_OFF + TS*BB*DLAT)

typedef unsigned long long ull;

// packed f32x2 helpers (each lane is an independent IEEE fp32 RN op —
// bit-exact vs scalar FFMA; only throughput changes)
__device__ __forceinline__ ull pack2(float lo, float hi) {
    ull r; asm("mov.b64 %0, {%1, %2};" : "=l"(r) : "f"(lo), "f"(hi)); return r;
}
__device__ __forceinline__ ull fma2(ull a, ull b, ull c) {
    ull d; asm("fma.rn.f32x2 %0, %1, %2, %3;" : "=l"(d) : "l"(a), "l"(b), "l"(c)); return d;
}
__device__ __forceinline__ ull add2(ull a, ull b) {
    ull d; asm("add.rn.f32x2 %0, %1, %2;" : "=l"(d) : "l"(a), "l"(b)); return d;
}
__device__ __forceinline__ float2 unpack2(ull v) {
    float2 f; asm("mov.b64 {%0, %1}, %2;" : "=f"(f.x), "=f"(f.y) : "l"(v)); return f;
}

// persistent state across kernels of the scan
__device__ float g_x[BB * DFEAT];    // x(t) = tanh(x_in @ W_pre + b_pre)
__device__ float g_xin[BB * DOBS];   // x_in(t)

// ---------------------------------------------------------------------------
// Fused dual-GEMM phase kernel.
// A = [x | h_src] (B x 1024). acc1 = A@W1, acc2 = A@W2 for a 32x32 tile of
// each matrix. Accumulators are f32x2 pairs over (col c0, col c0+1); the
// per-32-k-stage partials fold into a master (pairwise-ish summation), and the
// epilogue transcendentals run in double, rounded once to fp32.
// PHASE 0: g/theta/h (writes hs[t], thetas[t]); PHASE 1: y (writes ys[t]).
// grid = (16, 8); 128 threads; each thread: 4 rows x 2 cols x 2 matrices.
// ---------------------------------------------------------------------------
template <int PHASE>
__global__ __launch_bounds__(128) void phase_kernel(
    const float* __restrict__ W1, const float* __restrict__ b1,
    const float* __restrict__ W2, const float* __restrict__ b2,
    const float* __restrict__ noise_t,  // [B][DLAT] slice (phase 0 only)
    const float* __restrict__ h_src,    // [B][512]; nullptr => zeros (t==0)
    float* __restrict__ out1,           // hs[t] or ys[t] slice
    float* __restrict__ out_th)         // thetas[t] slice (phase 0)
{
    __shared__ float As[2][32][36];   // [k][row], padded
    __shared__ float B1s[2][32][32];  // [k][col]
    __shared__ float B2s[2][32][32];

    const int tid = threadIdx.x;
    const int m0 = blockIdx.y * 32;
    const int n0 = blockIdx.x * 32;
    const int r0 = (tid >> 4) * 4;  // 0..28
    const int c0 = (tid & 15) * 2;  // 0..30 (even -> 8B-aligned b64 pair)

    const int nstage = (h_src == nullptr) ? 16 : 32;  // K=512 at t==0 phase A

    ull acc1[4] = {0ull, 0ull, 0ull, 0ull};   // (0.f, 0.f) bit pattern
    ull acc2[4] = {0ull, 0ull, 0ull, 0ull};

    auto loadA = [&](int stage, int buf) {
        const int k0 = stage * 32;
        const float* src;
        int kbase;
        if (k0 < 512) { src = g_x;   kbase = k0; }
        else          { src = h_src; kbase = k0 - 512; }
#pragma unroll
        for (int i = 0; i < 2; i++) {
            int idx = tid + i * 128;      // 0..255 float4 slots
            int row = idx >> 3, q = idx & 7;
            float4 v = *(const float4*)&src[(size_t)(m0 + row) * 512 + kbase + q * 4];
            As[buf][q * 4 + 0][row] = v.x;
            As[buf][q * 4 + 1][row] = v.y;
            As[buf][q * 4 + 2][row] = v.z;
            As[buf][q * 4 + 3][row] = v.w;
        }
    };
    auto loadB = [&](int stage, int buf) {
        const int k0 = stage * 32;
#pragma unroll
        for (int i = 0; i < 2; i++) {
            int idx = tid + i * 128;
            int k = idx >> 3, q = idx & 7;
            *(float4*)&B1s[buf][k][q * 4] =
                *(const float4*)&W1[(size_t)(k0 + k) * 512 + n0 + q * 4];
            *(float4*)&B2s[buf][k][q * 4] =
                *(const float4*)&W2[(size_t)(k0 + k) * 512 + n0 + q * 4];
        }
    };

    loadA(0, 0);
    loadB(0, 0);
    __syncthreads();

    for (int s = 0; s < nstage; s++) {
        const int buf = s & 1;
        if (s + 1 < nstage) { loadA(s + 1, buf ^ 1); loadB(s + 1, buf ^ 1); }

        // stage-local partial accumulators (shorter rounding chains)
        ull p1[4] = {0ull, 0ull, 0ull, 0ull};
        ull p2[4] = {0ull, 0ull, 0ull, 0ull};
#pragma unroll
        for (int kk = 0; kk < 32; kk++) {
            float4 a = *(const float4*)&As[buf][kk][r0];
            ull w1p = *(const ull*)&B1s[buf][kk][c0];   // (w1[c0], w1[c0+1])
            ull w2p = *(const ull*)&B2s[buf][kk][c0];
            ull a0 = pack2(a.x, a.x);
            ull a1 = pack2(a.y, a.y);
            ull a2 = pack2(a.z, a.z);
            ull a3 = pack2(a.w, a.w);
            p1[0] = fma2(a0, w1p, p1[0]);
            p2[0] = fma2(a0, w2p, p2[0]);
            p1[1] = fma2(a1, w1p, p1[1]);
            p2[1] = fma2(a1, w2p, p2[1]);
            p1[2] = fma2(a2, w1p, p1[2]);
            p2[2] = fma2(a2, w2p, p2[2]);
            p1[3] = fma2(a3, w1p, p1[3]);
            p2[3] = fma2(a3, w2p, p2[3]);
        }
#pragma unroll
        for (int i = 0; i < 4; i++) {
            acc1[i] = add2(acc1[i], p1[i]);
            acc2[i] = add2(acc2[i], p2[i]);
        }
        __syncthreads();
    }

#pragma unroll
    for (int i = 0; i < 4; i++) {
        const int b = m0 + r0 + i;
        float2 v1 = unpack2(acc1[i]);
        float2 v2 = unpack2(acc2[i]);
        float a1v[2] = {v1.x, v1.y};
        float a2v[2] = {v2.x, v2.y};
#pragma unroll
        for (int c = 0; c < 2; c++) {
            const int n = n0 + c0 + c;
            if (PHASE == 0) {
                double z = (double)a1v[c] + (double)b1[n]
                         + (double)noise_t[b * DLAT + n];
                float th = (z > 0.0) ? 1.f : 0.f;
                double g  = (z > 0.0) ? tanh(z) : 0.0;
                double hp = h_src ? (double)h_src[b * DLAT + n] : 0.0;
                double rl = (double)a2v[c] + (double)b2[n];
                float h = (float)(g * tanh(rl) + (1.0 - g) * hp);
                out1[b * DLAT + n]   = h;
                out_th[b * DLAT + n] = th;
            } else {
                double p = (double)a1v[c] + (double)b1[n];
                double o = (double)a2v[c] + (double)b2[n];
                float y = (float)(tanh(p) / (1.0 + exp(-o)));
                out1[b * DLAT + n] = y;
            }
        }
    }
}

// ---------------------------------------------------------------------------
// Output + next-step-prep kernel. grid = 32 blocks x 256 threads, 8 rows/block.
// finish (y_t != null): out_pre = ys[t] @ W_out + b_out; out = x_in + out_pre;
//                       writes outs[t], delta_outs[t].
// prep   (obs_n != null): x_in(t+1) = m ? obs : out;  x(t+1) = tanh(x_in@W_pre+b).
// ---------------------------------------------------------------------------
__global__ __launch_bounds__(256) void out_kernel(
    const float* __restrict__ y_t,
    const float* __restrict__ W_out, const float* __restrict__ b_out,
    const float* __restrict__ obs_n,   // obs[t+1] slice, or nullptr
    const float* __restrict__ mask_n,  // sampling_mask[t+1] slice
    const float* __restrict__ W_pre, const float* __restrict__ b_pre,
    float* __restrict__ outs_t, float* __restrict__ douts_t,
    int force_m)
{
    __shared__ float ysm[8][512];
    __shared__ float outm[8][64];
    __shared__ float xinm[8][64];

    const int tid = threadIdx.x;
    const int rows0 = blockIdx.x * 8;

    if (y_t) {
#pragma unroll
        for (int i = 0; i < 4; i++) {
            int idx = tid + i * 256;  // 0..1023 float4 slots (8 rows x 128)
            int r = idx >> 7, q = idx & 127;
            *(float4*)&ysm[r][q * 4] =
                *(const float4*)&y_t[(size_t)(rows0 + r) * 512 + q * 4];
        }
        __syncthreads();

        const int r = tid >> 6;   // 0..3  (handles rows r and r+4)
        const int o = tid & 63;
        float acc0 = 0.f;
        float acc1 = 0.f;
        for (int fc = 0; fc < 512; fc += 64) {
            float pa0 = 0.f, pa1 = 0.f;
#pragma unroll 8
            for (int f = fc; f < fc + 64; f++) {
                float w = W_out[f * 64 + o];
                pa0 += ysm[r][f] * w;
                pa1 += ysm[r + 4][f] * w;
            }
            acc0 += pa0;
            acc1 += pa1;
        }
        acc0 += b_out[o];
        acc1 += b_out[o];
        const int b0 = rows0 + r, b1 = rows0 + r + 4;
        float out0 = g_xin[b0 * 64 + o] + acc0;
        float out1 = g_xin[b1 * 64 + o] + acc1;
        outs_t[b0 * 64 + o] = out0;
        outs_t[b1 * 64 + o] = out1;
        douts_t[b0 * 64 + o] = acc0;
        douts_t[b1 * 64 + o] = acc1;
        outm[r][o] = out0;
        outm[r + 4][o] = out1;
        __syncthreads();
    }

    if (obs_n) {
        const int r = tid >> 6;
        const int o = tid & 63;
#pragma unroll
        for (int i = 0; i < 2; i++) {
            int rr = r + i * 4;
            int b = rows0 + rr;
            float m = force_m ? 1.f : ((mask_n[b] < 0.5f) ? 1.f : 0.f);
            float xin = (m != 0.f) ? obs_n[b * 64 + o] : outm[rr][o];
            g_xin[b * 64 + o] = xin;
            xinm[rr][o] = xin;
        }
        __syncthreads();

        // x = tanh(x_in @ W_pre + b_pre): 8 rows x 512 feats
        const int r2 = tid >> 5;            // 0..7
        const int f0 = (tid & 31) * 16;     // 16 contiguous feats per thread
        float accM[16];
#pragma unroll
        for (int j = 0; j < 16; j++) accM[j] = 0.f;
        for (int oc = 0; oc < 64; oc += 16) {
            float accP[16];
#pragma unroll
            for (int j = 0; j < 16; j++) accP[j] = 0.f;
#pragma unroll
            for (int o2i = 0; o2i < 16; o2i++) {
                int o2 = oc + o2i;
                float xv = xinm[r2][o2];
                const float4* wp = (const float4*)&W_pre[o2 * 512 + f0];
#pragma unroll
                for (int j4 = 0; j4 < 4; j4++) {
                    float4 w = wp[j4];
                    accP[j4 * 4 + 0] += xv * w.x;
                    accP[j4 * 4 + 1] += xv * w.y;
                    accP[j4 * 4 + 2] += xv * w.z;
                    accP[j4 * 4 + 3] += xv * w.w;
                }
            }
#pragma unroll
            for (int j = 0; j < 16; j++) accM[j] += accP[j];
        }
#pragma unroll
        for (int j = 0; j < 16; j++)
            g_x[(size_t)(rows0 + r2) * 512 + f0 + j] =
                (float)tanh((double)accM[j] + (double)b_pre[f0 + j]);
    }
}

// ---------------------------------------------------------------------------
extern "C" void kernel_launch(void* const* d_in, const int* in_sizes, int n_in,
                              void* d_out, int out_size)
{
    (void)in_sizes; (void)n_in; (void)out_size;
    const float* obs   = (const float*)d_in[0];
    const float* smask = (const float*)d_in[1];
    const float* noise = (const float*)d_in[2];
    const float* W_pre = (const float*)d_in[3];
    const float* b_pre = (const float*)d_in[4];
    const float* Wg    = (const float*)d_in[5];
    const float* bg    = (const float*)d_in[6];
    const float* Wr    = (const float*)d_in[7];
    const float* br    = (const float*)d_in[8];
    const float* Wp    = (const float*)d_in[9];
    const float* bp    = (const float*)d_in[10];
    const float* Wo    = (const float*)d_in[11];
    const float* bo    = (const float*)d_in[12];
    const float* W_out = (const float*)d_in[13];
    const float* b_out = (const float*)d_in[14];

    float* out  = (float*)d_out;
    float* outs = out + OUTS_OFF;
    float* hs   = out + HS_OFF;
    float* ths  = out + TH_OFF;
    float* ys   = out + YS_OFF;
    float* dos_ = out + DO_OFF;

    dim3 pgrid(16, 8);

    // t = 0 prep: x_in(0) = obs[0] (mask forced to 1), x(0) = tanh(x_in @ W_pre + b)
    out_kernel<<<32, 256>>>(nullptr, W_out, b_out,
                            obs, smask, W_pre, b_pre,
                            nullptr, nullptr, /*force_m=*/1);

    for (int t = 0; t < TS; t++) {
        const float* hprev = (t == 0) ? nullptr : hs + (size_t)(t - 1) * BB * DLAT;
        float* ht  = hs  + (size_t)t * BB * DLAT;
        float* tht = ths + (size_t)t * BB * DLAT;
        float* yt  = ys  + (size_t)t * BB * DLAT;

        phase_kernel<0><<<pgrid, 128>>>(Wg, bg, Wr, br,
                                        noise + (size_t)t * BB * DLAT,
                                        hprev, ht, tht);
        phase_kernel<1><<<pgrid, 128>>>(Wp, bp, Wo, bo,
                                        nullptr, ht, yt, nullptr);

        const float* obs_n  = (t + 1 < TS) ? obs + (size_t)(t + 1) * BB * DOBS : nullptr;
        const float* mask_n = (t + 1 < TS) ? smask + (size_t)(t + 1) * BB : nullptr;
        out_kernel<<<32, 256>>>(yt, W_out, b_out,
                                obs_n, mask_n, W_pre, b_pre,
                                outs + (size_t)t * BB * DOUTD,
                                dos_ + (size_t)t * BB * DOUTD,
                                /*force_m=*/0);
    }
}

// round 5
// speedup vs baseline: 1.1702x; 1.1702x over previous
#include <cuda_runtime.h>

#define TS    100
#define BB    256
#define DOBS  64
#define DFEAT 512
#define DLAT  512
#define DOUTD 64

// d_out layout (element offsets): outs, hs, thetas, ys, delta_outs
#define OUTS_OFF 0
#define HS_OFF   (TS*BB*DOUTD)
#define TH_OFF   (HS_OFF + TS*BB*DLAT)
#define YS_OFF   (TH_OFF + TS*BB*DLAT)
#define DO_OFF   (YS_OFF + TS*BB*DLAT)

typedef unsigned long long ull;

// packed f32x2 helpers (each lane is an independent IEEE fp32 RN op)
__device__ __forceinline__ ull fma2(ull a, ull b, ull c) {
    ull d; asm("fma.rn.f32x2 %0, %1, %2, %3;" : "=l"(d) : "l"(a), "l"(b), "l"(c)); return d;
}
__device__ __forceinline__ ull add2(ull a, ull b) {
    ull d; asm("add.rn.f32x2 %0, %1, %2;" : "=l"(d) : "l"(a), "l"(b)); return d;
}
__device__ __forceinline__ float2 unpack2(ull v) {
    float2 f; asm("mov.b64 {%0, %1}, %2;" : "=f"(f.x), "=f"(f.y) : "l"(v)); return f;
}

// persistent state across kernels of the scan
__device__ float g_x[BB * DFEAT];    // x(t) = tanh(x_in @ W_pre + b_pre)
__device__ float g_xin[BB * DOBS];   // x_in(t)

// ---------------------------------------------------------------------------
// Fused dual-GEMM phase kernel.
// A = [x | h_src] (B x 1024). acc1 = A@W1, acc2 = A@W2 for a 32x32 tile.
// A is stored DUPLICATED in smem ([k][2*row], [k][2*row+1]) so a single
// LDS.128 yields two ready f32x2 broadcast pairs — no pack movs in the
// mainloop (12 issue slots per k-iter instead of 15). FFMA2 values/order
// are bit-identical to the R4 kernel.
// PHASE 0: g/theta/h (writes hs[t], thetas[t]); PHASE 1: y (writes ys[t]).
// grid = (16, 8); 128 threads; each thread: 4 rows x 2 cols x 2 matrices.
// ---------------------------------------------------------------------------
template <int PHASE>
__global__ __launch_bounds__(128) void phase_kernel(
    const float* __restrict__ W1, const float* __restrict__ b1,
    const float* __restrict__ W2, const float* __restrict__ b2,
    const float* __restrict__ noise_t,  // [B][DLAT] slice (phase 0 only)
    const float* __restrict__ h_src,    // [B][512]; nullptr => zeros (t==0)
    float* __restrict__ out1,           // hs[t] or ys[t] slice
    float* __restrict__ out_th)         // thetas[t] slice (phase 0)
{
    __shared__ float As[2][32][72];   // duplicated: [k][2*row+{0,1}], 288B rows
    __shared__ float B1s[2][32][32];  // [k][col]
    __shared__ float B2s[2][32][32];

    const int tid = threadIdx.x;
    const int m0 = blockIdx.y * 32;
    const int n0 = blockIdx.x * 32;
    const int r0 = (tid >> 4) * 4;  // 0..28
    const int c0 = (tid & 15) * 2;  // 0..30 (even -> 8B-aligned b64 pair)

    const int nstage = (h_src == nullptr) ? 16 : 32;  // K=512 at t==0 phase A

    ull acc1[4] = {0ull, 0ull, 0ull, 0ull};   // (0.f, 0.f) bit pattern
    ull acc2[4] = {0ull, 0ull, 0ull, 0ull};

    auto loadA = [&](int stage, int buf) {
        const int k0 = stage * 32;
        const float* src;
        int kbase;
        if (k0 < 512) { src = g_x;   kbase = k0; }
        else          { src = h_src; kbase = k0 - 512; }
#pragma unroll
        for (int i = 0; i < 2; i++) {
            int idx = tid + i * 128;      // 0..255 float4 slots
            int row = idx >> 3, q = idx & 7;
            float4 v = *(const float4*)&src[(size_t)(m0 + row) * 512 + kbase + q * 4];
            float2* p0 = (float2*)&As[buf][q * 4 + 0][2 * row];
            float2* p1 = (float2*)&As[buf][q * 4 + 1][2 * row];
            float2* p2 = (float2*)&As[buf][q * 4 + 2][2 * row];
            float2* p3 = (float2*)&As[buf][q * 4 + 3][2 * row];
            *p0 = make_float2(v.x, v.x);
            *p1 = make_float2(v.y, v.y);
            *p2 = make_float2(v.z, v.z);
            *p3 = make_float2(v.w, v.w);
        }
    };
    auto loadB = [&](int stage, int buf) {
        const int k0 = stage * 32;
#pragma unroll
        for (int i = 0; i < 2; i++) {
            int idx = tid + i * 128;
            int k = idx >> 3, q = idx & 7;
            *(float4*)&B1s[buf][k][q * 4] =
                *(const float4*)&W1[(size_t)(k0 + k) * 512 + n0 + q * 4];
            *(float4*)&B2s[buf][k][q * 4] =
                *(const float4*)&W2[(size_t)(k0 + k) * 512 + n0 + q * 4];
        }
    };

    loadA(0, 0);
    loadB(0, 0);
    __syncthreads();

    for (int s = 0; s < nstage; s++) {
        const int buf = s & 1;
        if (s + 1 < nstage) { loadA(s + 1, buf ^ 1); loadB(s + 1, buf ^ 1); }

        // stage-local partial accumulators (shorter rounding chains)
        ull p1[4] = {0ull, 0ull, 0ull, 0ull};
        ull p2[4] = {0ull, 0ull, 0ull, 0ull};
#pragma unroll
        for (int kk = 0; kk < 32; kk++) {
            // duplicated pairs: one 16B LDS gives (a[r],a[r]),(a[r+1],a[r+1])
            ulonglong2 a01 = *(const ulonglong2*)&As[buf][kk][2 * r0];
            ulonglong2 a23 = *(const ulonglong2*)&As[buf][kk][2 * r0 + 4];
            ull w1p = *(const ull*)&B1s[buf][kk][c0];   // (w1[c0], w1[c0+1])
            ull w2p = *(const ull*)&B2s[buf][kk][c0];
            p1[0] = fma2(a01.x, w1p, p1[0]);
            p2[0] = fma2(a01.x, w2p, p2[0]);
            p1[1] = fma2(a01.y, w1p, p1[1]);
            p2[1] = fma2(a01.y, w2p, p2[1]);
            p1[2] = fma2(a23.x, w1p, p1[2]);
            p2[2] = fma2(a23.x, w2p, p2[2]);
            p1[3] = fma2(a23.y, w1p, p1[3]);
            p2[3] = fma2(a23.y, w2p, p2[3]);
        }
#pragma unroll
        for (int i = 0; i < 4; i++) {
            acc1[i] = add2(acc1[i], p1[i]);
            acc2[i] = add2(acc2[i], p2[i]);
        }
        __syncthreads();
    }

#pragma unroll
    for (int i = 0; i < 4; i++) {
        const int b = m0 + r0 + i;
        float2 v1 = unpack2(acc1[i]);
        float2 v2 = unpack2(acc2[i]);
        float a1v[2] = {v1.x, v1.y};
        float a2v[2] = {v2.x, v2.y};
#pragma unroll
        for (int c = 0; c < 2; c++) {
            const int n = n0 + c0 + c;
            if (PHASE == 0) {
                double z = (double)a1v[c] + (double)b1[n]
                         + (double)noise_t[b * DLAT + n];
                float th = (z > 0.0) ? 1.f : 0.f;
                double g  = (z > 0.0) ? tanh(z) : 0.0;
                double hp = h_src ? (double)h_src[b * DLAT + n] : 0.0;
                double rl = (double)a2v[c] + (double)b2[n];
                float h = (float)(g * tanh(rl) + (1.0 - g) * hp);
                out1[b * DLAT + n]   = h;
                out_th[b * DLAT + n] = th;
            } else {
                double p = (double)a1v[c] + (double)b1[n];
                double o = (double)a2v[c] + (double)b2[n];
                float y = (float)(tanh(p) / (1.0 + exp(-o)));
                out1[b * DLAT + n] = y;
            }
        }
    }
}

// ---------------------------------------------------------------------------
// Output + next-step-prep kernel, v2: 128 blocks x 256 threads, 2 rows/block
// (4x the blocks of v1; short partial chains; deep LDG batches for MLP).
// finish (y_t != null): out_pre = ys[t] @ W_out + b_out; out = x_in + out_pre.
// prep   (obs_n != null): x_in(t+1) = m ? obs : out;  x(t+1) = tanh(x_in@W_pre+b).
// ---------------------------------------------------------------------------
__global__ __launch_bounds__(256) void out_kernel(
    const float* __restrict__ y_t,
    const float* __restrict__ W_out, const float* __restrict__ b_out,
    const float* __restrict__ obs_n,   // obs[t+1] slice, or nullptr
    const float* __restrict__ mask_n,  // sampling_mask[t+1] slice
    const float* __restrict__ W_pre, const float* __restrict__ b_pre,
    float* __restrict__ outs_t, float* __restrict__ douts_t,
    int force_m)
{
    __shared__ float ysm[2][512];
    __shared__ float red[2][64];    // half-1 K-partials
    __shared__ float outm[2][64];
    __shared__ float xinm[2][64];

    const int tid = threadIdx.x;
    const int b0 = blockIdx.x * 2;

    if (y_t) {
        // load 2 rows of y (256 float4 slots)
        {
            int r = tid >> 7, q = tid & 127;
            *(float4*)&ysm[r][q * 4] =
                *(const float4*)&y_t[(size_t)(b0 + r) * 512 + q * 4];
        }
        __syncthreads();

        // thread: o = col, r = row, half = K-half (256 each, 4 chunks of 64)
        const int o = tid & 63;
        const int rh = tid >> 6;      // 0..3
        const int r = rh & 1;
        const int half = rh >> 1;
        float acc = 0.f;
        const int fbase = half * 256;
        for (int fc = 0; fc < 256; fc += 64) {
            float pa = 0.f;
#pragma unroll 16
            for (int f = fbase + fc; f < fbase + fc + 64; f++) {
                pa += ysm[r][f] * W_out[f * 64 + o];
            }
            acc += pa;
        }
        if (half == 1) red[r][o] = acc;
        __syncthreads();
        if (half == 0) {
            float tot = acc + red[r][o] + b_out[o];
            const int b = b0 + r;
            float outv = g_xin[b * 64 + o] + tot;
            outs_t[b * 64 + o]  = outv;
            douts_t[b * 64 + o] = tot;
            outm[r][o] = outv;
        }
        __syncthreads();
    }

    if (obs_n) {
        // x_in for the 2 rows (first 128 threads)
        if (tid < 128) {
            const int r = tid >> 6;
            const int o = tid & 63;
            const int b = b0 + r;
            float m = force_m ? 1.f : ((mask_n[b] < 0.5f) ? 1.f : 0.f);
            float xin = (m != 0.f) ? obs_n[b * 64 + o] : outm[r][o];
            g_xin[b * 64 + o] = xin;
            xinm[r][o] = xin;
        }
        __syncthreads();

        // x = tanh(x_in @ W_pre + b_pre): 2 rows x 512 feats; thread = 4 feats
        const int r2 = tid >> 7;            // 0..1
        const int f0 = (tid & 127) * 4;     // 4 contiguous feats
        float accM[4] = {0.f, 0.f, 0.f, 0.f};
        for (int oc = 0; oc < 64; oc += 16) {
            float accP[4] = {0.f, 0.f, 0.f, 0.f};
#pragma unroll
            for (int o2i = 0; o2i < 16; o2i++) {
                int o2 = oc + o2i;
                float xv = xinm[r2][o2];
                float4 w = *(const float4*)&W_pre[o2 * 512 + f0];
                accP[0] += xv * w.x;
                accP[1] += xv * w.y;
                accP[2] += xv * w.z;
                accP[3] += xv * w.w;
            }
#pragma unroll
            for (int j = 0; j < 4; j++) accM[j] += accP[j];
        }
#pragma unroll
        for (int j = 0; j < 4; j++)
            g_x[(size_t)(b0 + r2) * 512 + f0 + j] =
                (float)tanh((double)accM[j] + (double)b_pre[f0 + j]);
    }
}

// ---------------------------------------------------------------------------
extern "C" void kernel_launch(void* const* d_in, const int* in_sizes, int n_in,
                              void* d_out, int out_size)
{
    (void)in_sizes; (void)n_in; (void)out_size;
    const float* obs   = (const float*)d_in[0];
    const float* smask = (const float*)d_in[1];
    const float* noise = (const float*)d_in[2];
    const float* W_pre = (const float*)d_in[3];
    const float* b_pre = (const float*)d_in[4];
    const float* Wg    = (const float*)d_in[5];
    const float* bg    = (const float*)d_in[6];
    const float* Wr    = (const float*)d_in[7];
    const float* br    = (const float*)d_in[8];
    const float* Wp    = (const float*)d_in[9];
    const float* bp    = (const float*)d_in[10];
    const float* Wo    = (const float*)d_in[11];
    const float* bo    = (const float*)d_in[12];
    const float* W_out = (const float*)d_in[13];
    const float* b_out = (const float*)d_in[14];

    float* out  = (float*)d_out;
    float* outs = out + OUTS_OFF;
    float* hs   = out + HS_OFF;
    float* ths  = out + TH_OFF;
    float* ys   = out + YS_OFF;
    float* dos_ = out + DO_OFF;

    dim3 pgrid(16, 8);

    // t = 0 prep: x_in(0) = obs[0] (mask forced to 1), x(0) = tanh(x_in @ W_pre + b)
    out_kernel<<<128, 256>>>(nullptr, W_out, b_out,
                             obs, smask, W_pre, b_pre,
                             nullptr, nullptr, /*force_m=*/1);

    for (int t = 0; t < TS; t++) {
        const float* hprev = (t == 0) ? nullptr : hs + (size_t)(t - 1) * BB * DLAT;
        float* ht  = hs  + (size_t)t * BB * DLAT;
        float* tht = ths + (size_t)t * BB * DLAT;
        float* yt  = ys  + (size_t)t * BB * DLAT;

        phase_kernel<0><<<pgrid, 128>>>(Wg, bg, Wr, br,
                                        noise + (size_t)t * BB * DLAT,
                                        hprev, ht, tht);
        phase_kernel<1><<<pgrid, 128>>>(Wp, bp, Wo, bo,
                                        nullptr, ht, yt, nullptr);

        const float* obs_n  = (t + 1 < TS) ? obs + (size_t)(t + 1) * BB * DOBS : nullptr;
        const float* mask_n = (t + 1 < TS) ? smask + (size_t)(t + 1) * BB : nullptr;
        out_kernel<<<128, 256>>>(yt, W_out, b_out,
                                 obs_n, mask_n, W_pre, b_pre,
                                 outs + (size_t)t * BB * DOUTD,
                                 dos_ + (size_t)t * BB * DOUTD,
                                 /*force_m=*/0);
    }
}